// round 1
// baseline (speedup 1.0000x reference)
#include <cuda_runtime.h>
#include <math.h>

// ---------------------------------------------------------------------------
// Scratch (device globals; no allocation in kernel_launch)
// ---------------------------------------------------------------------------
__device__ float g_feat1[2 * 512 * 4096];
__device__ float g_feat2[2 * 512 * 4096];
__device__ float g_q[2 * 64 * 4096];
__device__ float g_k[2 * 64 * 4096];
__device__ float g_v[2 * 512 * 4096];
__device__ float g_energy[2 * 4096 * 4096];     // 134 MB PAM attention logits
__device__ float g_sa_feat[2 * 512 * 4096];
__device__ float g_sc_feat[2 * 512 * 4096];
__device__ float g_sa_conv[2 * 512 * 4096];
__device__ float g_cam_e[2 * 512 * 512];
__device__ float g_scale[4 * 512];
__device__ float g_bias[4 * 512];

// ---------------------------------------------------------------------------
// Fold BN (inference) into per-channel scale/bias: y = x*inv + (b - m*inv)
// sets: 0=bn5a, 1=bn5c, 2=bn51, 3=bn52
// ---------------------------------------------------------------------------
__global__ void fold_bn_kernel(
    const float* s0, const float* b0, const float* m0, const float* v0,
    const float* s1, const float* b1, const float* m1, const float* v1,
    const float* s2, const float* b2, const float* m2, const float* v2,
    const float* s3, const float* b3, const float* m3, const float* v3)
{
    const float* S[4] = {s0, s1, s2, s3};
    const float* B[4] = {b0, b1, b2, b3};
    const float* M[4] = {m0, m1, m2, m3};
    const float* V[4] = {v0, v1, v2, v3};
    int set = blockIdx.x;
    int c = threadIdx.x;  // 0..511
    float inv = rsqrtf(V[set][c] + 1e-5f) * S[set][c];
    g_scale[set * 512 + c] = inv;
    g_bias[set * 512 + c]  = B[set][c] - M[set][c] * inv;
}

// ---------------------------------------------------------------------------
// 3x3 conv (pad 1) + folded BN + ReLU (+ optional post-ReLU addend), Cout=512.
// Block computes [64 co] x [one image row of 64 px]. 128 threads,
// per-thread 8co x 4px register tile. K-chunk = 8 input channels (72 MACs).
// Grid: (Cout/64, 64 rows, B)
// ---------------------------------------------------------------------------
__global__ __launch_bounds__(128) void conv3x3_bn_relu(
    const float* __restrict__ x, const float* __restrict__ w,
    int Cin, int bnset,
    const float* __restrict__ addend, float* __restrict__ out)
{
    __shared__ float ws[72][64];       // [k = ci_local*9 + dy*3 + dx][co_local]
    __shared__ float xs[8][3][68];     // [ci_local][row dy][col (gx = c-1)]

    const int coBase = blockIdx.x * 64;
    const int y      = blockIdx.y;
    const int bb     = blockIdx.z;
    const int tid    = threadIdx.x;
    const int tc     = tid >> 4;       // 0..7  -> co group of 8
    const int tn     = tid & 15;       // 0..15 -> px group of 4
    const int co0l   = tc * 8;
    const int px0    = tn * 4;

    float acc[8][4];
#pragma unroll
    for (int i = 0; i < 8; i++)
#pragma unroll
        for (int j = 0; j < 4; j++) acc[i][j] = 0.f;

    const float* xb = x + (size_t)bb * Cin * 4096;

    // weight-load assignment: 2 threads per co_local, 36 contiguous floats each
    const int co_l = tid >> 1;
    const int half = tid & 1;
    const float* wrow = w + (size_t)(coBase + co_l) * Cin * 9;

    for (int ciB = 0; ciB < Cin; ciB += 8) {
        // ---- load weights: 8 ci x 9 taps, contiguous in global per co ----
        {
            const float* wp = wrow + (size_t)ciB * 9 + half * 36;
#pragma unroll
            for (int j = 0; j < 36; j++) ws[half * 36 + j][co_l] = wp[j];
        }
        // ---- load input tile: 8 ci x 3 rows x 66 cols (zero-padded) ----
        for (int e = tid; e < 8 * 3 * 66; e += 128) {
            int ci = e / 198;
            int r  = (e / 66) % 3;
            int c  = e % 66;
            int gy = y - 1 + r;
            int gx = c - 1;
            float v = 0.f;
            if ((unsigned)gy < 64u && (unsigned)gx < 64u)
                v = xb[((ciB + ci) * 64 + gy) * 64 + gx];
            xs[ci][r][c] = v;
        }
        __syncthreads();

        for (int kc = 0; kc < 8; kc++) {
#pragma unroll
            for (int dy = 0; dy < 3; dy++) {
                float xf[6];
#pragma unroll
                for (int i = 0; i < 6; i++) xf[i] = xs[kc][dy][px0 + i];
#pragma unroll
                for (int dx = 0; dx < 3; dx++) {
                    const int kk = kc * 9 + dy * 3 + dx;
                    const float4 w0 = *(const float4*)&ws[kk][co0l];
                    const float4 w1 = *(const float4*)&ws[kk][co0l + 4];
                    float wv8[8] = {w0.x, w0.y, w0.z, w0.w, w1.x, w1.y, w1.z, w1.w};
#pragma unroll
                    for (int i = 0; i < 8; i++)
#pragma unroll
                        for (int j = 0; j < 4; j++)
                            acc[i][j] += wv8[i] * xf[dx + j];
                }
            }
        }
        __syncthreads();
    }

    // ---- epilogue: BN + ReLU (+ addend) ----
#pragma unroll
    for (int i = 0; i < 8; i++) {
        const int co = coBase + co0l + i;
        const float s  = g_scale[bnset * 512 + co];
        const float bi = g_bias[bnset * 512 + co];
        const size_t base = (((size_t)bb * 512 + co) * 64 + y) * 64;
#pragma unroll
        for (int j = 0; j < 4; j++) {
            float v = fmaxf(acc[i][j] * s + bi, 0.f);
            if (addend) v += addend[base + px0 + j];
            out[base + px0 + j] = v;
        }
    }
}

// ---------------------------------------------------------------------------
// Tiled SGEMM: C[m][n] = sum_k a(m,k)*b(k,n), 64x64 tile, BK=16, 128 threads.
//   AM==0:     a(m,k) = A[m*lda + k]      AM==1: a(m,k) = A[k*lda + m]
//   BMODE==1:  b(k,n) = B[k*ldb + n]   BMODE==0: b(k,n) = B[n*ldb + k]
// EP: 0 = none, 1 = +bias[m], 2 = gamma[0]*acc + add[b*sAdd + m*N + n]
// All M,N multiples of 64; K multiple of 16. ldc == N. Grid (M/64, N/64, B).
// ---------------------------------------------------------------------------
template <int AM, int BMODE, int EP>
__global__ __launch_bounds__(128) void gemm_kernel(
    const float* __restrict__ A, const float* __restrict__ Bm,
    float* __restrict__ C, int N, int K, int lda, int ldb,
    long sA, long sB, long sC,
    const float* __restrict__ bias, const float* __restrict__ gamma,
    const float* __restrict__ add, long sAdd)
{
    const int b = blockIdx.z;
    A  += (size_t)b * sA;
    Bm += (size_t)b * sB;
    C  += (size_t)b * sC;

    const int mBase = blockIdx.x * 64;
    const int nBase = blockIdx.y * 64;

    __shared__ float As[16][68];
    __shared__ float Bs[16][68];

    float acc[8][4];
#pragma unroll
    for (int i = 0; i < 8; i++)
#pragma unroll
        for (int j = 0; j < 4; j++) acc[i][j] = 0.f;

    const int tid = threadIdx.x;
    const int tc = tid >> 4;   // 0..7
    const int tn = tid & 15;   // 0..15

    for (int kb = 0; kb < K; kb += 16) {
        // ---- stage A tile -> As[k][m] ----
        if (AM == 0) {
            const int m  = tid >> 1;
            const int ko = (tid & 1) * 8;
            const float* p = A + (size_t)(mBase + m) * lda + kb + ko;
            float4 v0 = *(const float4*)p;
            float4 v1 = *(const float4*)(p + 4);
            As[ko + 0][m] = v0.x; As[ko + 1][m] = v0.y;
            As[ko + 2][m] = v0.z; As[ko + 3][m] = v0.w;
            As[ko + 4][m] = v1.x; As[ko + 5][m] = v1.y;
            As[ko + 6][m] = v1.z; As[ko + 7][m] = v1.w;
        } else {
            const int k  = tid >> 3;
            const int mo = (tid & 7) * 8;
            const float* p = A + (size_t)(kb + k) * lda + mBase + mo;
            *(float4*)&As[k][mo]     = *(const float4*)p;
            *(float4*)&As[k][mo + 4] = *(const float4*)(p + 4);
        }
        // ---- stage B tile -> Bs[k][n] ----
        if (BMODE == 0) {
            const int n  = tid >> 1;
            const int ko = (tid & 1) * 8;
            const float* p = Bm + (size_t)(nBase + n) * ldb + kb + ko;
            float4 v0 = *(const float4*)p;
            float4 v1 = *(const float4*)(p + 4);
            Bs[ko + 0][n] = v0.x; Bs[ko + 1][n] = v0.y;
            Bs[ko + 2][n] = v0.z; Bs[ko + 3][n] = v0.w;
            Bs[ko + 4][n] = v1.x; Bs[ko + 5][n] = v1.y;
            Bs[ko + 6][n] = v1.z; Bs[ko + 7][n] = v1.w;
        } else {
            const int k  = tid >> 3;
            const int no = (tid & 7) * 8;
            const float* p = Bm + (size_t)(kb + k) * ldb + nBase + no;
            *(float4*)&Bs[k][no]     = *(const float4*)p;
            *(float4*)&Bs[k][no + 4] = *(const float4*)(p + 4);
        }
        __syncthreads();

#pragma unroll
        for (int k = 0; k < 16; k++) {
            float4 a0 = *(const float4*)&As[k][tc * 8];
            float4 a1 = *(const float4*)&As[k][tc * 8 + 4];
            float4 bf = *(const float4*)&Bs[k][tn * 4];
            float av[8] = {a0.x, a0.y, a0.z, a0.w, a1.x, a1.y, a1.z, a1.w};
            float bv[4] = {bf.x, bf.y, bf.z, bf.w};
#pragma unroll
            for (int i = 0; i < 8; i++)
#pragma unroll
                for (int j = 0; j < 4; j++)
                    acc[i][j] += av[i] * bv[j];
        }
        __syncthreads();
    }

    const int n0 = nBase + tn * 4;
#pragma unroll
    for (int i = 0; i < 8; i++) {
        const int m = mBase + tc * 8 + i;
        const size_t row = (size_t)m * N;
#pragma unroll
        for (int j = 0; j < 4; j++) {
            float v = acc[i][j];
            if (EP == 1) v += bias[m];
            if (EP == 2) v = gamma[0] * v + add[(size_t)b * sAdd + row + n0 + j];
            C[row + n0 + j] = v;
        }
    }
}

// ---------------------------------------------------------------------------
// Row softmax, row length 4096, in place. One block (256 thr) per row.
// 16 elements per thread held in registers -> 1 read + 1 write per element.
// ---------------------------------------------------------------------------
__global__ void softmax4096_kernel(float* __restrict__ e)
{
    float* p = e + (size_t)blockIdx.x * 4096;
    const int tid = threadIdx.x;

    float4 v[4];
    float mx = -1e30f;
#pragma unroll
    for (int i = 0; i < 4; i++) {
        v[i] = *(const float4*)&p[i * 1024 + tid * 4];
        mx = fmaxf(mx, fmaxf(fmaxf(v[i].x, v[i].y), fmaxf(v[i].z, v[i].w)));
    }
    // block max
    __shared__ float red[8];
#pragma unroll
    for (int off = 16; off; off >>= 1) mx = fmaxf(mx, __shfl_xor_sync(0xffffffffu, mx, off));
    if ((tid & 31) == 0) red[tid >> 5] = mx;
    __syncthreads();
    mx = red[0];
#pragma unroll
    for (int i = 1; i < 8; i++) mx = fmaxf(mx, red[i]);
    __syncthreads();

    float s = 0.f;
#pragma unroll
    for (int i = 0; i < 4; i++) {
        v[i].x = __expf(v[i].x - mx); v[i].y = __expf(v[i].y - mx);
        v[i].z = __expf(v[i].z - mx); v[i].w = __expf(v[i].w - mx);
        s += v[i].x + v[i].y + v[i].z + v[i].w;
    }
#pragma unroll
    for (int off = 16; off; off >>= 1) s += __shfl_xor_sync(0xffffffffu, s, off);
    if ((tid & 31) == 0) red[tid >> 5] = s;
    __syncthreads();
    s = 0.f;
#pragma unroll
    for (int i = 0; i < 8; i++) s += red[i];
    const float inv = 1.f / s;
#pragma unroll
    for (int i = 0; i < 4; i++) {
        v[i].x *= inv; v[i].y *= inv; v[i].z *= inv; v[i].w *= inv;
        *(float4*)&p[i * 1024 + tid * 4] = v[i];
    }
}

// ---------------------------------------------------------------------------
// CAM softmax over rows of 512: attn = softmax(rowmax - e) == exp(rowmin - e)/sum
// One block (128 thr) per row, in place.
// ---------------------------------------------------------------------------
__global__ void softmax512_cam_kernel(float* __restrict__ e)
{
    float* p = e + (size_t)blockIdx.x * 512;
    const int tid = threadIdx.x;

    float4 v = *(const float4*)&p[tid * 4];
    float mn = fminf(fminf(v.x, v.y), fminf(v.z, v.w));
    __shared__ float red[4];
#pragma unroll
    for (int off = 16; off; off >>= 1) mn = fminf(mn, __shfl_xor_sync(0xffffffffu, mn, off));
    if ((tid & 31) == 0) red[tid >> 5] = mn;
    __syncthreads();
    mn = fminf(fminf(red[0], red[1]), fminf(red[2], red[3]));
    __syncthreads();

    v.x = __expf(mn - v.x); v.y = __expf(mn - v.y);
    v.z = __expf(mn - v.z); v.w = __expf(mn - v.w);
    float s = v.x + v.y + v.z + v.w;
#pragma unroll
    for (int off = 16; off; off >>= 1) s += __shfl_xor_sync(0xffffffffu, s, off);
    if ((tid & 31) == 0) red[tid >> 5] = s;
    __syncthreads();
    s = red[0] + red[1] + red[2] + red[3];
    const float inv = 1.f / s;
    v.x *= inv; v.y *= inv; v.z *= inv; v.w *= inv;
    *(float4*)&p[tid * 4] = v;
}

// ---------------------------------------------------------------------------
// Launch
// ---------------------------------------------------------------------------
extern "C" void kernel_launch(void* const* d_in, const int* in_sizes, int n_in,
                              void* d_out, int out_size)
{
    (void)in_sizes; (void)n_in; (void)out_size;

    const float* x         = (const float*)d_in[0];
    const float* w5a       = (const float*)d_in[1];
    const float* w5c       = (const float*)d_in[6];
    const float* wq        = (const float*)d_in[11];
    const float* bq        = (const float*)d_in[12];
    const float* wk        = (const float*)d_in[13];
    const float* bk        = (const float*)d_in[14];
    const float* wv        = (const float*)d_in[15];
    const float* bv        = (const float*)d_in[16];
    const float* gamma_pam = (const float*)d_in[17];
    const float* gamma_cam = (const float*)d_in[18];
    const float* w51       = (const float*)d_in[19];
    const float* w52       = (const float*)d_in[24];
    float* out = (float*)d_out;

    float *feat1, *feat2, *q, *k, *v, *energy, *sa_feat, *sc_feat, *sa_conv, *cam_e;
    cudaGetSymbolAddress((void**)&feat1,   g_feat1);
    cudaGetSymbolAddress((void**)&feat2,   g_feat2);
    cudaGetSymbolAddress((void**)&q,       g_q);
    cudaGetSymbolAddress((void**)&k,       g_k);
    cudaGetSymbolAddress((void**)&v,       g_v);
    cudaGetSymbolAddress((void**)&energy,  g_energy);
    cudaGetSymbolAddress((void**)&sa_feat, g_sa_feat);
    cudaGetSymbolAddress((void**)&sc_feat, g_sc_feat);
    cudaGetSymbolAddress((void**)&sa_conv, g_sa_conv);
    cudaGetSymbolAddress((void**)&cam_e,   g_cam_e);

    // 0) fold BN params (sets: 0=bn5a, 1=bn5c, 2=bn51, 3=bn52)
    fold_bn_kernel<<<4, 512>>>(
        (const float*)d_in[2],  (const float*)d_in[3],  (const float*)d_in[4],  (const float*)d_in[5],
        (const float*)d_in[7],  (const float*)d_in[8],  (const float*)d_in[9],  (const float*)d_in[10],
        (const float*)d_in[20], (const float*)d_in[21], (const float*)d_in[22], (const float*)d_in[23],
        (const float*)d_in[25], (const float*)d_in[26], (const float*)d_in[27], (const float*)d_in[28]);

    const dim3 cgrid(8, 64, 2);  // (Cout/64, rows, B)

    // 1) feat1 = CBR(x, w5a)   2) feat2 = CBR(x, w5c)
    conv3x3_bn_relu<<<cgrid, 128>>>(x, w5a, 2048, 0, nullptr, feat1);
    conv3x3_bn_relu<<<cgrid, 128>>>(x, w5c, 2048, 1, nullptr, feat2);

    const long F = 512L * 4096;   // feature batch stride
    const long Q = 64L * 4096;
    const long E = 4096L * 4096;

    // 3) q, k, v (1x1 convs = GEMMs with bias)
    gemm_kernel<0, 1, 1><<<dim3(1, 64, 2), 128>>>(wq, feat1, q, 4096, 512, 512, 4096,
                                                  0, F, Q, bq, nullptr, nullptr, 0);
    gemm_kernel<0, 1, 1><<<dim3(1, 64, 2), 128>>>(wk, feat1, k, 4096, 512, 512, 4096,
                                                  0, F, Q, bk, nullptr, nullptr, 0);
    gemm_kernel<0, 1, 1><<<dim3(8, 64, 2), 128>>>(wv, feat1, v, 4096, 512, 512, 4096,
                                                  0, F, F, bv, nullptr, nullptr, 0);

    // 4) energy[n][m] = sum_c q[c][n] k[c][m]
    gemm_kernel<1, 1, 0><<<dim3(64, 64, 2), 128>>>(q, k, energy, 4096, 64, 4096, 4096,
                                                   Q, Q, E, nullptr, nullptr, nullptr, 0);

    // 5) softmax over m (8192 rows total)
    softmax4096_kernel<<<8192, 256>>>(energy);

    // 6) sa_feat = gamma_pam * (v @ attn^T) + feat1
    gemm_kernel<0, 0, 2><<<dim3(8, 64, 2), 128>>>(v, energy, sa_feat, 4096, 4096, 4096, 4096,
                                                  F, E, F, nullptr, gamma_pam, feat1, F);

    // 7) CAM energy[c][d] = sum_n feat2[c][n] feat2[d][n]
    gemm_kernel<0, 0, 0><<<dim3(8, 8, 2), 128>>>(feat2, feat2, cam_e, 512, 4096, 4096, 4096,
                                                 F, F, 512L * 512, nullptr, nullptr, nullptr, 0);

    // 8) CAM softmax (softmax(rowmax - e) per row, 1024 rows)
    softmax512_cam_kernel<<<1024, 128>>>(cam_e);

    // 9) sc_feat = gamma_cam * (attn @ feat2) + feat2
    gemm_kernel<0, 1, 2><<<dim3(8, 64, 2), 128>>>(cam_e, feat2, sc_feat, 4096, 512, 512, 4096,
                                                  512L * 512, F, F, nullptr, gamma_cam, feat2, F);

    // 10) sa_conv = CBR(sa_feat, w51)
    conv3x3_bn_relu<<<cgrid, 128>>>(sa_feat, w51, 512, 2, nullptr, sa_conv);

    // 11) out = CBR(sc_feat, w52) + sa_conv
    conv3x3_bn_relu<<<cgrid, 128>>>(sc_feat, w52, 512, 3, sa_conv, out);
}

// round 2
// speedup vs baseline: 1.1561x; 1.1561x over previous
#include <cuda_runtime.h>
#include <math.h>

// ---------------------------------------------------------------------------
// Scratch (device globals; no allocation in kernel_launch)
// ---------------------------------------------------------------------------
__device__ float g_feat1[2 * 512 * 4096];
__device__ float g_feat2[2 * 512 * 4096];
__device__ float g_q[2 * 64 * 4096];
__device__ float g_k[2 * 64 * 4096];
__device__ float g_v[2 * 512 * 4096];
__device__ float g_energy[2 * 4096 * 4096];     // 134 MB PAM attention logits
__device__ float g_sa_feat[2 * 512 * 4096];
__device__ float g_sc_feat[2 * 512 * 4096];
__device__ float g_sa_conv[2 * 512 * 4096];
__device__ float g_cam_e[2 * 512 * 512];
__device__ float g_scale[4 * 512];
__device__ float g_bias[4 * 512];

// ---------------------------------------------------------------------------
// Fold BN (inference) into per-channel scale/bias: y = x*inv + (b - m*inv)
// sets: 0=bn5a, 1=bn5c, 2=bn51, 3=bn52
// ---------------------------------------------------------------------------
__global__ void fold_bn_kernel(
    const float* s0, const float* b0, const float* m0, const float* v0,
    const float* s1, const float* b1, const float* m1, const float* v1,
    const float* s2, const float* b2, const float* m2, const float* v2,
    const float* s3, const float* b3, const float* m3, const float* v3)
{
    const float* S[4] = {s0, s1, s2, s3};
    const float* B[4] = {b0, b1, b2, b3};
    const float* M[4] = {m0, m1, m2, m3};
    const float* V[4] = {v0, v1, v2, v3};
    int set = blockIdx.x;
    int c = threadIdx.x;  // 0..511
    float inv = rsqrtf(V[set][c] + 1e-5f) * S[set][c];
    g_scale[set * 512 + c] = inv;
    g_bias[set * 512 + c]  = B[set][c] - M[set][c] * inv;
}

// ---------------------------------------------------------------------------
// 3x3 conv (pad 1) + folded BN + ReLU (+ optional post-ReLU addend), Cout=512.
// Block computes [64 co] x [one image row of 64 px]. 128 threads,
// per-thread 8co x 4px register tile. K-chunk = 8 input channels (72 MACs).
// Grid: (Cout/64, 64 rows, B)
// ---------------------------------------------------------------------------
__global__ __launch_bounds__(128) void conv3x3_bn_relu(
    const float* __restrict__ x, const float* __restrict__ w,
    int Cin, int bnset,
    const float* __restrict__ addend, float* __restrict__ out)
{
    __shared__ float ws[72][64];       // [k = ci_local*9 + dy*3 + dx][co_local]
    __shared__ float xs[8][3][68];     // [ci_local][row dy][col (gx = c-1)]

    const int coBase = blockIdx.x * 64;
    const int y      = blockIdx.y;
    const int bb     = blockIdx.z;
    const int tid    = threadIdx.x;
    const int tc     = tid >> 4;       // 0..7  -> co group of 8
    const int tn     = tid & 15;       // 0..15 -> px group of 4
    const int co0l   = tc * 8;
    const int px0    = tn * 4;

    float acc[8][4];
#pragma unroll
    for (int i = 0; i < 8; i++)
#pragma unroll
        for (int j = 0; j < 4; j++) acc[i][j] = 0.f;

    const float* xb = x + (size_t)bb * Cin * 4096;

    // weight-load assignment: 2 threads per co_local, 36 contiguous floats each
    const int co_l = tid >> 1;
    const int half = tid & 1;
    const float* wrow = w + (size_t)(coBase + co_l) * Cin * 9;

    for (int ciB = 0; ciB < Cin; ciB += 8) {
        // ---- load weights: 8 ci x 9 taps, contiguous in global per co ----
        {
            const float* wp = wrow + (size_t)ciB * 9 + half * 36;
#pragma unroll
            for (int j = 0; j < 36; j++) ws[half * 36 + j][co_l] = wp[j];
        }
        // ---- load input tile: 8 ci x 3 rows x 66 cols (zero-padded) ----
        for (int e = tid; e < 8 * 3 * 66; e += 128) {
            int ci = e / 198;
            int r  = (e / 66) % 3;
            int c  = e % 66;
            int gy = y - 1 + r;
            int gx = c - 1;
            float v = 0.f;
            if ((unsigned)gy < 64u && (unsigned)gx < 64u)
                v = xb[((ciB + ci) * 64 + gy) * 64 + gx];
            xs[ci][r][c] = v;
        }
        __syncthreads();

        for (int kc = 0; kc < 8; kc++) {
#pragma unroll
            for (int dy = 0; dy < 3; dy++) {
                float xf[6];
#pragma unroll
                for (int i = 0; i < 6; i++) xf[i] = xs[kc][dy][px0 + i];
#pragma unroll
                for (int dx = 0; dx < 3; dx++) {
                    const int kk = kc * 9 + dy * 3 + dx;
                    const float4 w0 = *(const float4*)&ws[kk][co0l];
                    const float4 w1 = *(const float4*)&ws[kk][co0l + 4];
                    float wv8[8] = {w0.x, w0.y, w0.z, w0.w, w1.x, w1.y, w1.z, w1.w};
#pragma unroll
                    for (int i = 0; i < 8; i++)
#pragma unroll
                        for (int j = 0; j < 4; j++)
                            acc[i][j] += wv8[i] * xf[dx + j];
                }
            }
        }
        __syncthreads();
    }

    // ---- epilogue: BN + ReLU (+ addend) ----
#pragma unroll
    for (int i = 0; i < 8; i++) {
        const int co = coBase + co0l + i;
        const float s  = g_scale[bnset * 512 + co];
        const float bi = g_bias[bnset * 512 + co];
        const size_t base = (((size_t)bb * 512 + co) * 64 + y) * 64;
#pragma unroll
        for (int j = 0; j < 4; j++) {
            float v = fmaxf(acc[i][j] * s + bi, 0.f);
            if (addend) v += addend[base + px0 + j];
            out[base + px0 + j] = v;
        }
    }
}

// ---------------------------------------------------------------------------
// Tiled SGEMM: C[m][n] = sum_k a(m,k)*b(k,n), 64x64 tile, BK=16, 128 threads.
//   AM==0:     a(m,k) = A[m*lda + k]      AM==1: a(m,k) = A[k*lda + m]
//   BMODE==1:  b(k,n) = B[k*ldb + n]   BMODE==0: b(k,n) = B[n*ldb + k]
// EP: 0 = none, 1 = +bias[m], 2 = gamma[0]*acc + add[b*sAdd + m*N + n]
// All M,N multiples of 64; K multiple of 16. ldc == N. Grid (M/64, N/64, B).
// ---------------------------------------------------------------------------
template <int AM, int BMODE, int EP>
__global__ __launch_bounds__(128) void gemm_kernel(
    const float* __restrict__ A, const float* __restrict__ Bm,
    float* __restrict__ C, int N, int K, int lda, int ldb,
    long sA, long sB, long sC,
    const float* __restrict__ bias, const float* __restrict__ gamma,
    const float* __restrict__ add, long sAdd)
{
    const int b = blockIdx.z;
    A  += (size_t)b * sA;
    Bm += (size_t)b * sB;
    C  += (size_t)b * sC;

    const int mBase = blockIdx.x * 64;
    const int nBase = blockIdx.y * 64;

    __shared__ float As[16][68];
    __shared__ float Bs[16][68];

    float acc[8][4];
#pragma unroll
    for (int i = 0; i < 8; i++)
#pragma unroll
        for (int j = 0; j < 4; j++) acc[i][j] = 0.f;

    const int tid = threadIdx.x;
    const int tc = tid >> 4;   // 0..7
    const int tn = tid & 15;   // 0..15

    for (int kb = 0; kb < K; kb += 16) {
        // ---- stage A tile -> As[k][m] ----
        if (AM == 0) {
            const int m  = tid >> 1;
            const int ko = (tid & 1) * 8;
            const float* p = A + (size_t)(mBase + m) * lda + kb + ko;
            float4 v0 = *(const float4*)p;
            float4 v1 = *(const float4*)(p + 4);
            As[ko + 0][m] = v0.x; As[ko + 1][m] = v0.y;
            As[ko + 2][m] = v0.z; As[ko + 3][m] = v0.w;
            As[ko + 4][m] = v1.x; As[ko + 5][m] = v1.y;
            As[ko + 6][m] = v1.z; As[ko + 7][m] = v1.w;
        } else {
            const int k  = tid >> 3;
            const int mo = (tid & 7) * 8;
            const float* p = A + (size_t)(kb + k) * lda + mBase + mo;
            *(float4*)&As[k][mo]     = *(const float4*)p;
            *(float4*)&As[k][mo + 4] = *(const float4*)(p + 4);
        }
        // ---- stage B tile -> Bs[k][n] ----
        if (BMODE == 0) {
            const int n  = tid >> 1;
            const int ko = (tid & 1) * 8;
            const float* p = Bm + (size_t)(nBase + n) * ldb + kb + ko;
            float4 v0 = *(const float4*)p;
            float4 v1 = *(const float4*)(p + 4);
            Bs[ko + 0][n] = v0.x; Bs[ko + 1][n] = v0.y;
            Bs[ko + 2][n] = v0.z; Bs[ko + 3][n] = v0.w;
            Bs[ko + 4][n] = v1.x; Bs[ko + 5][n] = v1.y;
            Bs[ko + 6][n] = v1.z; Bs[ko + 7][n] = v1.w;
        } else {
            const int k  = tid >> 3;
            const int no = (tid & 7) * 8;
            const float* p = Bm + (size_t)(kb + k) * ldb + nBase + no;
            *(float4*)&Bs[k][no]     = *(const float4*)p;
            *(float4*)&Bs[k][no + 4] = *(const float4*)(p + 4);
        }
        __syncthreads();

#pragma unroll
        for (int k = 0; k < 16; k++) {
            float4 a0 = *(const float4*)&As[k][tc * 8];
            float4 a1 = *(const float4*)&As[k][tc * 8 + 4];
            float4 bf = *(const float4*)&Bs[k][tn * 4];
            float av[8] = {a0.x, a0.y, a0.z, a0.w, a1.x, a1.y, a1.z, a1.w};
            float bv[4] = {bf.x, bf.y, bf.z, bf.w};
#pragma unroll
            for (int i = 0; i < 8; i++)
#pragma unroll
                for (int j = 0; j < 4; j++)
                    acc[i][j] += av[i] * bv[j];
        }
        __syncthreads();
    }

    const int n0 = nBase + tn * 4;
#pragma unroll
    for (int i = 0; i < 8; i++) {
        const int m = mBase + tc * 8 + i;
        const size_t row = (size_t)m * N;
#pragma unroll
        for (int j = 0; j < 4; j++) {
            float v = acc[i][j];
            if (EP == 1) v += bias[m];
            if (EP == 2) v = gamma[0] * v + add[(size_t)b * sAdd + row + n0 + j];
            C[row + n0 + j] = v;
        }
    }
}

// ---------------------------------------------------------------------------
// Row softmax, row length 4096, in place. One block (256 thr) per row.
// 16 elements per thread held in registers -> 1 read + 1 write per element.
// ---------------------------------------------------------------------------
__global__ void softmax4096_kernel(float* __restrict__ e)
{
    float* p = e + (size_t)blockIdx.x * 4096;
    const int tid = threadIdx.x;

    float4 v[4];
    float mx = -1e30f;
#pragma unroll
    for (int i = 0; i < 4; i++) {
        v[i] = *(const float4*)&p[i * 1024 + tid * 4];
        mx = fmaxf(mx, fmaxf(fmaxf(v[i].x, v[i].y), fmaxf(v[i].z, v[i].w)));
    }
    // block max
    __shared__ float red[8];
#pragma unroll
    for (int off = 16; off; off >>= 1) mx = fmaxf(mx, __shfl_xor_sync(0xffffffffu, mx, off));
    if ((tid & 31) == 0) red[tid >> 5] = mx;
    __syncthreads();
    mx = red[0];
#pragma unroll
    for (int i = 1; i < 8; i++) mx = fmaxf(mx, red[i]);
    __syncthreads();

    float s = 0.f;
#pragma unroll
    for (int i = 0; i < 4; i++) {
        v[i].x = __expf(v[i].x - mx); v[i].y = __expf(v[i].y - mx);
        v[i].z = __expf(v[i].z - mx); v[i].w = __expf(v[i].w - mx);
        s += v[i].x + v[i].y + v[i].z + v[i].w;
    }
#pragma unroll
    for (int off = 16; off; off >>= 1) s += __shfl_xor_sync(0xffffffffu, s, off);
    if ((tid & 31) == 0) red[tid >> 5] = s;
    __syncthreads();
    s = 0.f;
#pragma unroll
    for (int i = 0; i < 8; i++) s += red[i];
    const float inv = 1.f / s;
#pragma unroll
    for (int i = 0; i < 4; i++) {
        v[i].x *= inv; v[i].y *= inv; v[i].z *= inv; v[i].w *= inv;
        *(float4*)&p[i * 1024 + tid * 4] = v[i];
    }
}

// ---------------------------------------------------------------------------
// CAM softmax over rows of 512: attn = softmax(rowmax - e) == exp(rowmin - e)/sum
// One block (128 thr) per row, in place.
// ---------------------------------------------------------------------------
__global__ void softmax512_cam_kernel(float* __restrict__ e)
{
    float* p = e + (size_t)blockIdx.x * 512;
    const int tid = threadIdx.x;

    float4 v = *(const float4*)&p[tid * 4];
    float mn = fminf(fminf(v.x, v.y), fminf(v.z, v.w));
    __shared__ float red[4];
#pragma unroll
    for (int off = 16; off; off >>= 1) mn = fminf(mn, __shfl_xor_sync(0xffffffffu, mn, off));
    if ((tid & 31) == 0) red[tid >> 5] = mn;
    __syncthreads();
    mn = fminf(fminf(red[0], red[1]), fminf(red[2], red[3]));
    __syncthreads();

    v.x = __expf(mn - v.x); v.y = __expf(mn - v.y);
    v.z = __expf(mn - v.z); v.w = __expf(mn - v.w);
    float s = v.x + v.y + v.z + v.w;
#pragma unroll
    for (int off = 16; off; off >>= 1) s += __shfl_xor_sync(0xffffffffu, s, off);
    if ((tid & 31) == 0) red[tid >> 5] = s;
    __syncthreads();
    s = red[0] + red[1] + red[2] + red[3];
    const float inv = 1.f / s;
    v.x *= inv; v.y *= inv; v.z *= inv; v.w *= inv;
    *(float4*)&p[tid * 4] = v;
}

// ---------------------------------------------------------------------------
// Launch
// ---------------------------------------------------------------------------
extern "C" void kernel_launch(void* const* d_in, const int* in_sizes, int n_in,
                              void* d_out, int out_size)
{
    (void)in_sizes; (void)n_in; (void)out_size;

    const float* x         = (const float*)d_in[0];
    const float* w5a       = (const float*)d_in[1];
    const float* w5c       = (const float*)d_in[6];
    const float* wq        = (const float*)d_in[11];
    const float* bq        = (const float*)d_in[12];
    const float* wk        = (const float*)d_in[13];
    const float* bk        = (const float*)d_in[14];
    const float* wv        = (const float*)d_in[15];
    const float* bv        = (const float*)d_in[16];
    const float* gamma_pam = (const float*)d_in[17];
    const float* gamma_cam = (const float*)d_in[18];
    const float* w51       = (const float*)d_in[19];
    const float* w52       = (const float*)d_in[24];
    float* out = (float*)d_out;

    float *feat1, *feat2, *q, *k, *v, *energy, *sa_feat, *sc_feat, *sa_conv, *cam_e;
    cudaGetSymbolAddress((void**)&feat1,   g_feat1);
    cudaGetSymbolAddress((void**)&feat2,   g_feat2);
    cudaGetSymbolAddress((void**)&q,       g_q);
    cudaGetSymbolAddress((void**)&k,       g_k);
    cudaGetSymbolAddress((void**)&v,       g_v);
    cudaGetSymbolAddress((void**)&energy,  g_energy);
    cudaGetSymbolAddress((void**)&sa_feat, g_sa_feat);
    cudaGetSymbolAddress((void**)&sc_feat, g_sc_feat);
    cudaGetSymbolAddress((void**)&sa_conv, g_sa_conv);
    cudaGetSymbolAddress((void**)&cam_e,   g_cam_e);

    // 0) fold BN params (sets: 0=bn5a, 1=bn5c, 2=bn51, 3=bn52)
    fold_bn_kernel<<<4, 512>>>(
        (const float*)d_in[2],  (const float*)d_in[3],  (const float*)d_in[4],  (const float*)d_in[5],
        (const float*)d_in[7],  (const float*)d_in[8],  (const float*)d_in[9],  (const float*)d_in[10],
        (const float*)d_in[20], (const float*)d_in[21], (const float*)d_in[22], (const float*)d_in[23],
        (const float*)d_in[25], (const float*)d_in[26], (const float*)d_in[27], (const float*)d_in[28]);

    const dim3 cgrid(8, 64, 2);  // (Cout/64, rows, B)

    // 1) feat1 = CBR(x, w5a)   2) feat2 = CBR(x, w5c)
    conv3x3_bn_relu<<<cgrid, 128>>>(x, w5a, 2048, 0, nullptr, feat1);
    conv3x3_bn_relu<<<cgrid, 128>>>(x, w5c, 2048, 1, nullptr, feat2);

    const long F = 512L * 4096;   // feature batch stride
    const long Q = 64L * 4096;
    const long E = 4096L * 4096;

    // 3) q, k, v (1x1 convs = GEMMs with bias)
    gemm_kernel<0, 1, 1><<<dim3(1, 64, 2), 128>>>(wq, feat1, q, 4096, 512, 512, 4096,
                                                  0, F, Q, bq, nullptr, nullptr, 0);
    gemm_kernel<0, 1, 1><<<dim3(1, 64, 2), 128>>>(wk, feat1, k, 4096, 512, 512, 4096,
                                                  0, F, Q, bk, nullptr, nullptr, 0);
    gemm_kernel<0, 1, 1><<<dim3(8, 64, 2), 128>>>(wv, feat1, v, 4096, 512, 512, 4096,
                                                  0, F, F, bv, nullptr, nullptr, 0);

    // 4) energy[n][m] = sum_c q[c][n] k[c][m]
    gemm_kernel<1, 1, 0><<<dim3(64, 64, 2), 128>>>(q, k, energy, 4096, 64, 4096, 4096,
                                                   Q, Q, E, nullptr, nullptr, nullptr, 0);

    // 5) softmax over m (8192 rows total)
    softmax4096_kernel<<<8192, 256>>>(energy);

    // 6) sa_feat = gamma_pam * (v @ attn^T) + feat1
    gemm_kernel<0, 0, 2><<<dim3(8, 64, 2), 128>>>(v, energy, sa_feat, 4096, 4096, 4096, 4096,
                                                  F, E, F, nullptr, gamma_pam, feat1, F);

    // 7) CAM energy[c][d] = sum_n feat2[c][n] feat2[d][n]
    gemm_kernel<0, 0, 0><<<dim3(8, 8, 2), 128>>>(feat2, feat2, cam_e, 512, 4096, 4096, 4096,
                                                 F, F, 512L * 512, nullptr, nullptr, nullptr, 0);

    // 8) CAM softmax (softmax(rowmax - e) per row, 1024 rows)
    softmax512_cam_kernel<<<1024, 128>>>(cam_e);

    // 9) sc_feat = gamma_cam * (attn @ feat2) + feat2
    gemm_kernel<0, 1, 2><<<dim3(8, 64, 2), 128>>>(cam_e, feat2, sc_feat, 4096, 512, 512, 4096,
                                                  512L * 512, F, F, nullptr, gamma_cam, feat2, F);

    // 10) sa_conv = CBR(sa_feat, w51)
    conv3x3_bn_relu<<<cgrid, 128>>>(sa_feat, w51, 512, 2, nullptr, sa_conv);

    // 11) out = CBR(sc_feat, w52) + sa_conv
    conv3x3_bn_relu<<<cgrid, 128>>>(sc_feat, w52, 512, 3, sa_conv, out);
}